// round 3
// baseline (speedup 1.0000x reference)
#include <cuda_runtime.h>
#include <math_constants.h>

#define BB 4
#define TT 4096
#define DD 1024
#define NROW (BB*TT)          // 16384

// ---- scratch (device globals: no allocations allowed) ----
__device__ float2 g_Q[NROW];
__device__ float2 g_K[NROW];
__device__ int    g_idx[NROW];      // flattened source row b*T + argmax_s
__device__ int    g_mark[NROW];
__device__ int    g_list[NROW];
__device__ int    g_count;
__device__ float  g_V[(size_t)NROW * DD];   // 64 MB, only unique rows written

static const unsigned FULL = 0xffffffffu;

// ---------------- kernel 1: Q,K projection (+ fused mark/count init) ----------
// 256 threads = 8 warps, warp per row. W_Q/W_K (16KB) staged in smem.
__global__ void qk_kernel(const float* __restrict__ x,
                          const float* __restrict__ WQ,
                          const float* __restrict__ WK) {
    __shared__ float4 swq0[256], swq1[256], swk0[256], swk1[256];
    const float4* WQ4 = (const float4*)WQ;
    const float4* WK4 = (const float4*)WK;
    int tid = threadIdx.x;
    swq0[tid] = WQ4[tid];
    swq1[tid] = WQ4[256 + tid];
    swk0[tid] = WK4[tid];
    swk1[tid] = WK4[256 + tid];
    __syncthreads();

    int warp = tid >> 5, lane = tid & 31;
    int row = blockIdx.x * 8 + warp;           // b*T + t
    const float4* x4 = (const float4*)x + (size_t)row * 256;

    float q0 = 0.f, q1 = 0.f, k0 = 0.f, k1 = 0.f;
#pragma unroll
    for (int j = 0; j < 8; ++j) {
        int d = lane + j * 32;
        float4 xv = x4[d];
        float4 a = swq0[d], b = swq1[d], c = swk0[d], e = swk1[d];
        q0 += xv.x*a.x + xv.y*a.y + xv.z*a.z + xv.w*a.w;
        q1 += xv.x*b.x + xv.y*b.y + xv.z*b.z + xv.w*b.w;
        k0 += xv.x*c.x + xv.y*c.y + xv.z*c.z + xv.w*c.w;
        k1 += xv.x*e.x + xv.y*e.y + xv.z*e.z + xv.w*e.w;
    }
#pragma unroll
    for (int off = 16; off; off >>= 1) {
        q0 += __shfl_xor_sync(FULL, q0, off);
        q1 += __shfl_xor_sync(FULL, q1, off);
        k0 += __shfl_xor_sync(FULL, k0, off);
        k1 += __shfl_xor_sync(FULL, k1, off);
    }
    if (lane == 0) {
        g_Q[row] = make_float2(q0, q1);
        g_K[row] = make_float2(k0, k1);
        g_mark[row] = 0;                       // fused init (argmax runs after)
        if (row == 0) g_count = 0;
    }
}

// ---------------- kernel 2: causal argmax, block-per-t ----------------
// grid (TT, BB), 128 threads. float4 loads: 2 K points per LDG.128.
// Reduction keeps (max score, min index) == jnp.argmax first occurrence.
__global__ void __launch_bounds__(128) argmax_kernel() {
    int b = blockIdx.y, t = blockIdx.x;
    float2 q = g_Q[b * TT + t];
    const float4* __restrict__ K4 = (const float4*)(g_K + b * TT); // pair i -> s=2i,2i+1

    float best = -CUDART_INF_F;
    int bi = 0x7fffffff;
    for (int i = threadIdx.x; 2 * i <= t; i += 128) {
        float4 kk = K4[i];
        int s0 = 2 * i;
        float sc0 = kk.x * q.x + kk.y * q.y;
        if (sc0 > best) { best = sc0; bi = s0; }
        if (s0 + 1 <= t) {
            float sc1 = kk.z * q.x + kk.w * q.y;
            if (sc1 > best) { best = sc1; bi = s0 + 1; }
        }
    }
#pragma unroll
    for (int off = 16; off; off >>= 1) {
        float ob = __shfl_xor_sync(FULL, best, off);
        int   oi = __shfl_xor_sync(FULL, bi,   off);
        if (ob > best || (ob == best && oi < bi)) { best = ob; bi = oi; }
    }
    __shared__ float sb[4];
    __shared__ int   si[4];
    int warp = threadIdx.x >> 5, lane = threadIdx.x & 31;
    if (lane == 0) { sb[warp] = best; si[warp] = bi; }
    __syncthreads();
    if (threadIdx.x == 0) {
#pragma unroll
        for (int w = 1; w < 4; ++w)
            if (sb[w] > best || (sb[w] == best && si[w] < bi)) { best = sb[w]; bi = si[w]; }
        int src = b * TT + bi;
        g_idx[b * TT + t] = src;
        if (atomicExch(&g_mark[src], 1) == 0) {
            int p = atomicAdd(&g_count, 1);
            g_list[p] = src;
        }
    }
}

// ---------------- kernel 3: V rows, W_V-stationary ----------------
// Grid = 128 blocks; block owns 8 e-rows of W_V staged ONCE in smem (32 KB).
// Warps loop over unique rows: x row -> registers (coalesced float4),
// 8 smem dot-products + butterfly reduce. W_V total traffic = 4 MB.
#define E_PER_BLK 8
__global__ void __launch_bounds__(256) vrows_kernel(const float* __restrict__ WV,
                                                    const float* __restrict__ x) {
    __shared__ float4 wv_s[E_PER_BLK * 256];   // 32 KB
    int eb = blockIdx.x * E_PER_BLK;
    for (int i = threadIdx.x; i < E_PER_BLK * 256; i += 256)
        wv_s[i] = ((const float4*)WV)[(size_t)eb * 256 + i];
    __syncthreads();

    int cnt = g_count;
    int warp = threadIdx.x >> 5, lane = threadIdx.x & 31;

    for (int ui = warp; ui < cnt; ui += 8) {
        int row = g_list[ui];
        const float4* xr = (const float4*)x + (size_t)row * 256;
        float4 xv[8];
#pragma unroll
        for (int j = 0; j < 8; ++j)
            xv[j] = __ldg(&xr[lane + j * 32]);

#pragma unroll
        for (int e = 0; e < E_PER_BLK; ++e) {
            float a = 0.f;
#pragma unroll
            for (int j = 0; j < 8; ++j) {
                float4 w = wv_s[e * 256 + lane + j * 32];
                a += w.x*xv[j].x + w.y*xv[j].y + w.z*xv[j].z + w.w*xv[j].w;
            }
#pragma unroll
            for (int off = 16; off; off >>= 1)
                a += __shfl_xor_sync(FULL, a, off);
            if (lane == 0)
                g_V[(size_t)row * DD + eb + e] = a;
        }
    }
}

// ---------------- kernel 4: gather to output ----------------
// 2048 blocks x 8 warps; warp copies one 4KB row; streaming stores
// (output never re-read -> don't pollute L2, keep it for hot g_V rows).
__global__ void gather_kernel(float* __restrict__ out) {
    int warp = threadIdx.x >> 5, lane = threadIdx.x & 31;
    int r = blockIdx.x * 8 + warp;          // destination row b*T + t
    int src = g_idx[r];
    const float4* v4 = (const float4*)g_V + (size_t)src * 256;
    float4* o4 = (float4*)out + (size_t)r * 256;
#pragma unroll
    for (int j = 0; j < 8; ++j) {
        float4 v = __ldg(&v4[lane + j * 32]);
        __stcs(&o4[lane + j * 32], v);
    }
}

extern "C" void kernel_launch(void* const* d_in, const int* in_sizes, int n_in,
                              void* d_out, int out_size) {
    const float* x  = (const float*)d_in[0];
    const float* WQ = (const float*)d_in[1];
    const float* WK = (const float*)d_in[2];
    const float* WV = (const float*)d_in[3];
    float* out = (float*)d_out;

    qk_kernel<<<NROW / 8, 256>>>(x, WQ, WK);
    argmax_kernel<<<dim3(TT, BB), 128>>>();
    vrows_kernel<<<DD / E_PER_BLK, 256>>>(WV, x);
    gather_kernel<<<NROW / 8, 256>>>(out);
}

// round 4
// speedup vs baseline: 1.1081x; 1.1081x over previous
#include <cuda_runtime.h>
#include <math_constants.h>

#define BB 4
#define TT 4096
#define DD 1024
#define NROW (BB*TT)          // 16384

// ---- scratch (device globals: no allocations allowed) ----
__device__ float2 g_Q[NROW];
__device__ float2 g_K[NROW];
__device__ unsigned long long g_best64[NROW]; // (ordered(score)<<32)|~s
__device__ int    g_idx[NROW];      // flattened source row b*T + argmax_s
__device__ int    g_mark[NROW];
__device__ int    g_list[NROW];
__device__ int    g_count;
__device__ float  g_V[(size_t)NROW * DD];   // 64 MB, only unique rows written

static const unsigned FULL = 0xffffffffu;

__device__ __forceinline__ unsigned ord_f32(float x) {
    unsigned u = __float_as_uint(x);
    return (u & 0x80000000u) ? ~u : (u | 0x80000000u);
}

// ---------------- kernel 1: Q,K projection (+ fused scratch init) ----------
// 256 threads = 8 warps, warp per row. W_Q/W_K (16KB) staged in smem.
__global__ void qk_kernel(const float* __restrict__ x,
                          const float* __restrict__ WQ,
                          const float* __restrict__ WK) {
    __shared__ float4 swq0[256], swq1[256], swk0[256], swk1[256];
    const float4* WQ4 = (const float4*)WQ;
    const float4* WK4 = (const float4*)WK;
    int tid = threadIdx.x;
    swq0[tid] = WQ4[tid];
    swq1[tid] = WQ4[256 + tid];
    swk0[tid] = WK4[tid];
    swk1[tid] = WK4[256 + tid];
    __syncthreads();

    int warp = tid >> 5, lane = tid & 31;
    int row = blockIdx.x * 8 + warp;           // b*T + t
    const float4* x4 = (const float4*)x + (size_t)row * 256;

    float q0 = 0.f, q1 = 0.f, k0 = 0.f, k1 = 0.f;
#pragma unroll
    for (int j = 0; j < 8; ++j) {
        int d = lane + j * 32;
        float4 xv = x4[d];
        float4 a = swq0[d], b = swq1[d], c = swk0[d], e = swk1[d];
        q0 += xv.x*a.x + xv.y*a.y + xv.z*a.z + xv.w*a.w;
        q1 += xv.x*b.x + xv.y*b.y + xv.z*b.z + xv.w*b.w;
        k0 += xv.x*c.x + xv.y*c.y + xv.z*c.z + xv.w*c.w;
        k1 += xv.x*e.x + xv.y*e.y + xv.z*e.z + xv.w*e.w;
    }
#pragma unroll
    for (int off = 16; off; off >>= 1) {
        q0 += __shfl_xor_sync(FULL, q0, off);
        q1 += __shfl_xor_sync(FULL, q1, off);
        k0 += __shfl_xor_sync(FULL, k0, off);
        k1 += __shfl_xor_sync(FULL, k1, off);
    }
    if (lane == 0) {
        g_Q[row] = make_float2(q0, q1);
        g_K[row] = make_float2(k0, k1);
        g_mark[row] = 0;
        g_best64[row] = 0ull;                  // < any real score encoding
        if (row == 0) g_count = 0;
    }
}

// ---------------- kernel 2: argmax, tile x chunk units ----------------
// Unit = (128-t tile, 1024-s chunk). 80 units/batch, grid (80, BB), 128 thr.
// Thread owns t = t0+tid, scans chunk from smem with hoisted bound.
// Merge via atomicMax of (ordered(score)<<32)|~s  -> max score, min s on tie.
__global__ void __launch_bounds__(128) argmax_kernel() {
    __shared__ float2 ks[1024];    // 8 KB
    int b = blockIdx.y;
    // decode unit -> (tile, chunk): group g (0..3) has 8 tiles x (g+1) chunks
    int u = blockIdx.x, g = 0, base = 0;
    while (u >= base + 8 * (g + 1)) { base += 8 * (g + 1); ++g; }
    int r = u - base;
    int ti = g * 8 + r / (g + 1);
    int chunk = r % (g + 1);
    int t0 = ti * 128, s0 = chunk * 1024;

    const float4* K4 = (const float4*)(g_K + b * TT + s0);
#pragma unroll
    for (int j = 0; j < 4; ++j)
        ((float4*)ks)[threadIdx.x + j * 128] = K4[threadIdx.x + j * 128];
    __syncthreads();

    int t = t0 + threadIdx.x;
    float2 q = g_Q[b * TT + t];
    int s_limit = t - s0 + 1;
    if (s_limit > 1024) s_limit = 1024;

    float best = -CUDART_INF_F;
    int bi = 0;
    for (int s = 0; s < s_limit; ++s) {        // ascending + strict > = first occ.
        float2 k = ks[s];
        float sc = k.x * q.x + k.y * q.y;
        if (sc > best) { best = sc; bi = s0 + s; }
    }
    unsigned long long enc =
        ((unsigned long long)ord_f32(best) << 32) | (unsigned)(~bi);
    atomicMax(&g_best64[b * TT + t], enc);
}

// ---------------- kernel 2b: decode argmax + build unique list -------------
__global__ void decode_kernel() {
    int i = blockIdx.x * 256 + threadIdx.x;
    if (i >= NROW) return;
    unsigned long long enc = g_best64[i];
    int s = (int)(~(unsigned)(enc & 0xffffffffull));
    int src = (i & ~(TT - 1)) | s;
    g_idx[i] = src;
    if (atomicExch(&g_mark[src], 1) == 0) {
        int p = atomicAdd(&g_count, 1);
        g_list[p] = src;
    }
}

// ---------------- kernel 3: V rows for unique indices (R2 version) ---------
// Work item = (unique_row, 64-e tile): cnt*16 items, grid-stride over 1184
// persistent blocks. Block: x row in smem; warp computes 8 e's as
// 2 x (4 simultaneous accumulators) for high MLP.
__global__ void __launch_bounds__(256) vrows_kernel(const float* __restrict__ WV,
                                                    const float* __restrict__ x) {
    __shared__ float4 xs[256];
    int cnt = g_count;
    int items = cnt * (DD / 64);               // cnt * 16
    int warp = threadIdx.x >> 5, lane = threadIdx.x & 31;

    for (int it = blockIdx.x; it < items; it += gridDim.x) {
        int ui   = it >> 4;
        int tile = it & 15;
        int row  = g_list[ui];

        __syncthreads();                       // protect xs reuse
        xs[threadIdx.x] = ((const float4*)x)[(size_t)row * 256 + threadIdx.x];
        __syncthreads();

        int ebase = tile * 64 + warp * 8;
#pragma unroll
        for (int half = 0; half < 2; ++half) {
            int e = ebase + half * 4;
            const float4* w0 = (const float4*)(WV + (size_t)(e + 0) * DD);
            const float4* w1 = (const float4*)(WV + (size_t)(e + 1) * DD);
            const float4* w2 = (const float4*)(WV + (size_t)(e + 2) * DD);
            const float4* w3 = (const float4*)(WV + (size_t)(e + 3) * DD);
            float a0 = 0.f, a1 = 0.f, a2 = 0.f, a3 = 0.f;
#pragma unroll
            for (int j = 0; j < 8; ++j) {
                int d = lane + j * 32;
                float4 xv = xs[d];
                float4 v0 = w0[d], v1 = w1[d], v2 = w2[d], v3 = w3[d];
                a0 += v0.x*xv.x + v0.y*xv.y + v0.z*xv.z + v0.w*xv.w;
                a1 += v1.x*xv.x + v1.y*xv.y + v1.z*xv.z + v1.w*xv.w;
                a2 += v2.x*xv.x + v2.y*xv.y + v2.z*xv.z + v2.w*xv.w;
                a3 += v3.x*xv.x + v3.y*xv.y + v3.z*xv.z + v3.w*xv.w;
            }
#pragma unroll
            for (int off = 16; off; off >>= 1) {
                a0 += __shfl_xor_sync(FULL, a0, off);
                a1 += __shfl_xor_sync(FULL, a1, off);
                a2 += __shfl_xor_sync(FULL, a2, off);
                a3 += __shfl_xor_sync(FULL, a3, off);
            }
            if (lane == 0) {
                float* dst = g_V + (size_t)row * DD + e;
                dst[0] = a0; dst[1] = a1; dst[2] = a2; dst[3] = a3;
            }
        }
    }
}

// ---------------- kernel 4: gather to output ----------------
// 2048 blocks x 8 warps; warp copies one 4KB row; streaming stores.
__global__ void gather_kernel(float* __restrict__ out) {
    int warp = threadIdx.x >> 5, lane = threadIdx.x & 31;
    int r = blockIdx.x * 8 + warp;          // destination row b*T + t
    int src = g_idx[r];
    const float4* v4 = (const float4*)g_V + (size_t)src * 256;
    float4* o4 = (float4*)out + (size_t)r * 256;
#pragma unroll
    for (int j = 0; j < 8; ++j) {
        float4 v = __ldg(&v4[lane + j * 32]);
        __stcs(&o4[lane + j * 32], v);
    }
}

extern "C" void kernel_launch(void* const* d_in, const int* in_sizes, int n_in,
                              void* d_out, int out_size) {
    const float* x  = (const float*)d_in[0];
    const float* WQ = (const float*)d_in[1];
    const float* WK = (const float*)d_in[2];
    const float* WV = (const float*)d_in[3];
    float* out = (float*)d_out;

    qk_kernel<<<NROW / 8, 256>>>(x, WQ, WK);
    argmax_kernel<<<dim3(80, BB), 128>>>();
    decode_kernel<<<NROW / 256, 256>>>();
    vrows_kernel<<<1184, 256>>>(WV, x);
    gather_kernel<<<NROW / 8, 256>>>(out);
}